// round 16
// baseline (speedup 1.0000x reference)
#include <cuda_runtime.h>
#include <cuda_fp16.h>
#include <cstdint>

namespace {
constexpr int B_  = 4;
constexpr int S_  = 2048;
constexpr int D_  = 1024;
constexpr int H_  = 16;
constexpr int M_  = B_ * S_;  // 8192
constexpr long long OUT_ELEMS  = (long long)M_ * D_;
constexpr long long ATTN_ELEMS = (long long)B_ * H_ * S_ * S_;
}

// ------------------------- device scratch (no allocs) -----------------------
__device__ half g_ah[M_ * D_];
__device__ half g_qf[M_ * D_], g_kf[M_ * D_], g_vf[M_ * D_];
__device__ half g_ch[M_ * D_];
__device__ half g_wq[D_ * D_], g_wk[D_ * D_], g_wv[D_ * D_], g_wo[D_ * D_];

// ----------------------------- helpers --------------------------------------
__device__ __forceinline__ uint32_t smem_u32(const void* p) {
    uint32_t a;
    asm("{ .reg .u64 t; cvta.to.shared.u64 t, %1; cvt.u32.u64 %0, t; }"
        : "=r"(a) : "l"(p));
    return a;
}

__device__ __forceinline__ void cp16(uint32_t s, const void* g) {
    asm volatile("cp.async.cg.shared.global [%0], [%1], 16;" :: "r"(s), "l"(g));
}
#define CP_COMMIT asm volatile("cp.async.commit_group;" ::: "memory")
#define CP_WAIT0  asm volatile("cp.async.wait_group 0;" ::: "memory")
#define CP_WAIT1  asm volatile("cp.async.wait_group 1;" ::: "memory")

#define LDSM_X4(r0, r1, r2, r3, addr) \
    asm volatile("ldmatrix.sync.aligned.m8n8.x4.shared.b16 {%0,%1,%2,%3}, [%4];" \
                 : "=r"(r0), "=r"(r1), "=r"(r2), "=r"(r3) : "r"(addr))

#define LDSM_X4T(r0, r1, r2, r3, addr) \
    asm volatile("ldmatrix.sync.aligned.m8n8.x4.trans.shared.b16 {%0,%1,%2,%3}, [%4];" \
                 : "=r"(r0), "=r"(r1), "=r"(r2), "=r"(r3) : "r"(addr))

__device__ __forceinline__ void mma_hf(float c[4], const uint32_t a[4],
                                       uint32_t b0, uint32_t b1) {
    asm volatile(
        "mma.sync.aligned.m16n8k16.row.col.f32.f16.f16.f32 "
        "{%0,%1,%2,%3}, {%4,%5,%6,%7}, {%8,%9}, {%0,%1,%2,%3};"
        : "+f"(c[0]), "+f"(c[1]), "+f"(c[2]), "+f"(c[3])
        : "r"(a[0]), "r"(a[1]), "r"(a[2]), "r"(a[3]), "r"(b0), "r"(b1));
}

// f16-accumulate variant (C = 2 packed half2 regs): 2x rate on fp32-half-rate dies
__device__ __forceinline__ void mma_hh(uint32_t c[2], const uint32_t a[4],
                                       uint32_t b0, uint32_t b1) {
    asm volatile(
        "mma.sync.aligned.m16n8k16.row.col.f16.f16.f16.f16 "
        "{%0,%1}, {%2,%3,%4,%5}, {%6,%7}, {%0,%1};"
        : "+r"(c[0]), "+r"(c[1])
        : "r"(a[0]), "r"(a[1]), "r"(a[2]), "r"(a[3]), "r"(b0), "r"(b1));
}

__device__ __forceinline__ uint32_t pack2h(float x, float y) {
    __half2 t = __floats2half2_rn(x, y);
    return *reinterpret_cast<uint32_t*>(&t);
}

// ---------------------------------------------------------------------------
// Fused fp32 -> fp16 cast of hidden_states + 4 weight matrices.
// ---------------------------------------------------------------------------
__global__ void cast_all_kernel(const float* __restrict__ hs,
                                const float* __restrict__ Wq,
                                const float* __restrict__ Wk,
                                const float* __restrict__ Wv,
                                const float* __restrict__ Wo,
                                half* __restrict__ ah,
                                half* __restrict__ wq, half* __restrict__ wk,
                                half* __restrict__ wv, half* __restrict__ wo)
{
    int i = blockIdx.x * blockDim.x + threadIdx.x;
    constexpr int MD = M_ * D_;           // 2^23
    constexpr int DD = D_ * D_;           // 2^20
    if (i < MD) {
        ah[i] = __float2half_rn(hs[i]);
    } else {
        int j = i - MD;
        int wsel = j >> 20;
        int off = j & (DD - 1);
        const float* src = (wsel == 0) ? Wq : (wsel == 1) ? Wk
                         : (wsel == 2) ? Wv : Wo;
        half* dst = (wsel == 0) ? wq : (wsel == 1) ? wk
                  : (wsel == 2) ? wv : wo;
        dst[off] = __float2half_rn(src[off]);
    }
}

// ---------------------------------------------------------------------------
// fp16 HMMA GEMM: C = A @ W^T + bias (exact R13 structure, 2 CTAs/SM).
// ---------------------------------------------------------------------------
struct GemmArgs {
    const half *Ah, *Wh;
    const float* bias;
    float* Cf;
    half* Cq;
};
struct GemmArgs3 { GemmArgs a[3]; };

__global__ void __launch_bounds__(256, 2) gemm_mma_kernel(GemmArgs3 args)
{
    constexpr int PA = 40;
    constexpr int BUFE = 128 * PA;
    constexpr int STAGE = 2 * BUFE;
    extern __shared__ __align__(16) half gsm[];

    const GemmArgs ga = args.a[blockIdx.z];

    const int tid = threadIdx.x;
    const int w = tid >> 5, lane = tid & 31, gid = lane >> 2, tig = lane & 3;
    const int bm = blockIdx.y * 128, bn = blockIdx.x * 128;
    const int m0 = (w >> 1) * 32, n0 = (w & 1) * 64;

    float c[2][8][4] = {};

    auto load_chunk = [&](int t, int buf) {
        int kc = t << 5;
        half* sA = gsm + buf * STAGE;
        half* sW = sA + BUFE;
#pragma unroll
        for (int i = 0; i < 2; ++i) {
            int idx = tid * 2 + i;
            int row = idx >> 2, q = idx & 3;
            size_t go = (size_t)row * 1024 + kc + q * 8;
            cp16(smem_u32(&sA[row * PA + q * 8]), ga.Ah + (size_t)bm * 1024 + go);
            cp16(smem_u32(&sW[row * PA + q * 8]), ga.Wh + (size_t)bn * 1024 + go);
        }
    };

    auto compute_chunk = [&](int buf) {
        const half* sA = gsm + buf * STAGE;
        const half* sW = sA + BUFE;
#pragma unroll
        for (int ks = 0; ks < 32; ks += 16) {
            uint32_t a[2][4];
#pragma unroll
            for (int mi = 0; mi < 2; ++mi) {
                int ro = (m0 + mi * 16 + (lane & 15)) * PA + ks + ((lane >> 4) << 3);
                LDSM_X4(a[mi][0], a[mi][1], a[mi][2], a[mi][3], smem_u32(&sA[ro]));
            }
#pragma unroll
            for (int p = 0; p < 4; ++p) {
                int br = n0 + p * 16 + (lane & 7) + ((lane >> 4) << 3);
                int bc = ks + (((lane >> 3) & 1) << 3);
                uint32_t b0, b1, b2, b3;
                LDSM_X4(b0, b1, b2, b3, smem_u32(&sW[br * PA + bc]));
                mma_hf(c[0][2 * p],     a[0], b0, b1);
                mma_hf(c[1][2 * p],     a[1], b0, b1);
                mma_hf(c[0][2 * p + 1], a[0], b2, b3);
                mma_hf(c[1][2 * p + 1], a[1], b2, b3);
            }
        }
    };

    load_chunk(0, 0); CP_COMMIT;
    load_chunk(1, 1); CP_COMMIT;

    for (int t = 0; t < 32; ++t) {
        if (t + 2 < 32) { CP_WAIT1; } else { CP_WAIT0; }
        __syncthreads();
        if (t + 2 < 32) { load_chunk(t + 2, (t + 2) % 3); CP_COMMIT; }
        compute_chunk(t % 3);
        __syncthreads();
    }

#pragma unroll
    for (int mi = 0; mi < 2; ++mi) {
#pragma unroll
        for (int ni = 0; ni < 8; ++ni) {
            int r0 = bm + m0 + mi * 16 + gid;
            int col = bn + n0 + ni * 8 + 2 * tig;
            float bv0 = ga.bias[col], bv1 = ga.bias[col + 1];
            float o00 = c[mi][ni][0] + bv0, o01 = c[mi][ni][1] + bv1;
            float o10 = c[mi][ni][2] + bv0, o11 = c[mi][ni][3] + bv1;
            if (ga.Cf) {
                *(float2*)&ga.Cf[(size_t)r0 * 1024 + col] = make_float2(o00, o01);
                *(float2*)&ga.Cf[(size_t)(r0 + 8) * 1024 + col] = make_float2(o10, o11);
            }
            if (ga.Cq) {
                *(uint32_t*)&ga.Cq[(size_t)r0 * 1024 + col]       = pack2h(o00, o01);
                *(uint32_t*)&ga.Cq[(size_t)(r0 + 8) * 1024 + col] = pack2h(o10, o11);
            }
        }
    }
}

// ---------------------------------------------------------------------------
// Two-phase fp16 flash attention (R13 structure; phase-1 S uses f16-acc MMA).
//   q-tile 64/CTA; 8 warps = 4 q-groups (16 rows) x 2 key-halves (32 keys).
//   3-stage K/V ring, one __syncthreads per chunk; launch_bounds(256,3).
// ---------------------------------------------------------------------------
__global__ void __launch_bounds__(256, 3) attn_fp16_kernel(
    const half* __restrict__ qf, const half* __restrict__ kf,
    const half* __restrict__ vf, const int* __restrict__ maskg,
    float* __restrict__ attn, half* __restrict__ ctxh)
{
    constexpr int P = 72;
    constexpr int KTILE = 64 * P;        // 4608 halves
    constexpr int STAGE = 2 * KTILE;     // K + V per ring stage
    constexpr int CTXP = 66;             // sCtx pitch (floats)
    extern __shared__ __align__(16) half hsm[];
    half* Qs  = hsm;                     // 64*72 = 4608 halves
    half* KV0 = hsm + 4608;              // 3 ring stages x (K,V)
    int*  sMask = (int*)(hsm + 4608 + 3 * STAGE);   // 2048 ints
    float* sL   = (float*)(sMask + 2048);           // 64 floats
    float* sCtx = (float*)KV0;           // aliases ring (post-loop)

    const int tid = threadIdx.x;
    const int w = tid >> 5, lane = tid & 31, gid = lane >> 2, tig = lane & 3;
    const int qt = blockIdx.x, h = blockIdx.y, b = blockIdx.z;
    const int q0 = qt * 64;
    const int qg = w >> 1, kh = w & 1;
    const int m0 = qg * 16;
    const int n0k = kh * 32;

    if (tid < 64) sL[tid] = 0.f;

    // ---- Q (64x64) + full mask row ----
    {
        size_t base = (size_t)(b * S_ + q0) * D_ + h * 64;
#pragma unroll
        for (int i = 0; i < 2; ++i) {
            int idx = tid * 2 + i;
            int row = idx >> 3, qq = idx & 7;
            cp16(smem_u32(&Qs[row * P + qq * 8]), qf + base + (size_t)row * D_ + qq * 8);
        }
#pragma unroll
        for (int i = 0; i < 2; ++i) {
            int j = tid * 2 + i;
            cp16(smem_u32(&sMask[j * 4]), maskg + b * S_ + j * 4);
        }
        CP_COMMIT;
    }

    auto load_k = [&](int kt, int st) {
        size_t kbase = (size_t)(b * S_ + kt * 64) * D_ + h * 64;
        half* Ks_ = KV0 + st * STAGE;
#pragma unroll
        for (int i = 0; i < 2; ++i) {
            int idx = tid * 2 + i;
            int row = idx >> 3, qq = idx & 7;
            cp16(smem_u32(&Ks_[row * P + qq * 8]), kf + kbase + (size_t)row * D_ + qq * 8);
        }
    };
    auto load_kv = [&](int kt, int st) {
        size_t kbase = (size_t)(b * S_ + kt * 64) * D_ + h * 64;
        half* Ks_ = KV0 + st * STAGE;
        half* Vs_ = Ks_ + KTILE;
#pragma unroll
        for (int i = 0; i < 2; ++i) {
            int idx = tid * 2 + i;
            int row = idx >> 3, qq = idx & 7;
            size_t go = kbase + (size_t)row * D_ + qq * 8;
            cp16(smem_u32(&Ks_[row * P + qq * 8]), kf + go);
            cp16(smem_u32(&Vs_[row * P + qq * 8]), vf + go);
        }
    };

    // fp32-acc S (phase 2: values written to attn)
    auto computeS = [&](const half* Ks_, float sc[4][4]) {
#pragma unroll
        for (int ks = 0; ks < 64; ks += 16) {
            uint32_t a[4];
            LDSM_X4(a[0], a[1], a[2], a[3],
                    smem_u32(&Qs[(m0 + (lane & 15)) * P + ks + ((lane >> 4) << 3)]));
#pragma unroll
            for (int p = 0; p < 2; ++p) {
                int br = n0k + p * 16 + (lane & 7) + ((lane >> 4) << 3);
                int bc = ks + (((lane >> 3) & 1) << 3);
                uint32_t b0, b1, b2, b3;
                LDSM_X4(b0, b1, b2, b3, smem_u32(&Ks_[br * P + bc]));
                mma_hf(sc[2 * p],     a, b0, b1);
                mma_hf(sc[2 * p + 1], a, b2, b3);
            }
        }
    };

    // f16-acc S (phase 1: only feeds l; per-row error ~1e-4 after averaging)
    auto computeS16 = [&](const half* Ks_, uint32_t sch[4][2]) {
#pragma unroll
        for (int ks = 0; ks < 64; ks += 16) {
            uint32_t a[4];
            LDSM_X4(a[0], a[1], a[2], a[3],
                    smem_u32(&Qs[(m0 + (lane & 15)) * P + ks + ((lane >> 4) << 3)]));
#pragma unroll
            for (int p = 0; p < 2; ++p) {
                int br = n0k + p * 16 + (lane & 7) + ((lane >> 4) << 3);
                int bc = ks + (((lane >> 3) & 1) << 3);
                uint32_t b0, b1, b2, b3;
                LDSM_X4(b0, b1, b2, b3, smem_u32(&Ks_[br * P + bc]));
                mma_hh(sch[2 * p],     a, b0, b1);
                mma_hh(sch[2 * p + 1], a, b2, b3);
            }
        }
    };

    // ================= phase 1: l (f16-acc S) =================
    load_k(0, 0); CP_COMMIT;
    load_k(1, 1); CP_COMMIT;
    float lacc[2] = {};

    for (int kt = 0; kt < 32; ++kt) {
        if (kt < 31) { CP_WAIT1; } else { CP_WAIT0; }
        __syncthreads();
        if (kt + 2 < 32) { load_k(kt + 2, (kt + 2) % 3); CP_COMMIT; }

        uint32_t sch[4][2] = {};
        computeS16(KV0 + (kt % 3) * STAGE, sch);

        const int* mk = sMask + kt * 64;
#pragma unroll
        for (int ni = 0; ni < 4; ++ni) {
            int cc = n0k + ni * 8 + 2 * tig;
            bool k0m = mk[cc] != 0, k1m = mk[cc + 1] != 0;
            float2 f0 = __half22float2(*reinterpret_cast<__half2*>(&sch[ni][0]));
            float2 f1 = __half22float2(*reinterpret_cast<__half2*>(&sch[ni][1]));
            lacc[0] += (k0m ? __expf(f0.x * 0.125f) : 0.f)
                     + (k1m ? __expf(f0.y * 0.125f) : 0.f);
            lacc[1] += (k0m ? __expf(f1.x * 0.125f) : 0.f)
                     + (k1m ? __expf(f1.y * 0.125f) : 0.f);
        }
    }

#pragma unroll
    for (int hf = 0; hf < 2; ++hf) {
        float v = lacc[hf];
        v += __shfl_xor_sync(0xffffffffu, v, 1);
        v += __shfl_xor_sync(0xffffffffu, v, 2);
        if (tig == 0) atomicAdd(&sL[m0 + gid + hf * 8], v);
    }
    __syncthreads();

    float invl[2];
#pragma unroll
    for (int hf = 0; hf < 2; ++hf) {
        float lv = sL[m0 + gid + hf * 8];
        invl[hf] = (lv > 0.f) ? (1.f / lv) : 0.f;
    }

    // ================= phase 2: attn + ctx (fp32-acc) =================
    load_kv(0, 0); CP_COMMIT;
    load_kv(1, 1); CP_COMMIT;

    float ctxc[8][4] = {};

    for (int kt = 0; kt < 32; ++kt) {
        if (kt < 31) { CP_WAIT1; } else { CP_WAIT0; }
        __syncthreads();
        if (kt + 2 < 32) { load_kv(kt + 2, (kt + 2) % 3); CP_COMMIT; }

        const half* Ks_ = KV0 + (kt % 3) * STAGE;
        const half* Vs_ = Ks_ + KTILE;

        float sc[4][4] = {};
        computeS(Ks_, sc);

        const int* mk = sMask + kt * 64;
        uint32_t ah[2][4];
#pragma unroll
        for (int ni = 0; ni < 4; ++ni) {
            int cc = n0k + ni * 8 + 2 * tig;
            bool k0m = mk[cc] != 0, k1m = mk[cc + 1] != 0;
            float p00 = k0m ? (__expf(sc[ni][0] * 0.125f) * invl[0]) : 0.f;
            float p01 = k1m ? (__expf(sc[ni][1] * 0.125f) * invl[0]) : 0.f;
            float p10 = k0m ? (__expf(sc[ni][2] * 0.125f) * invl[1]) : 0.f;
            float p11 = k1m ? (__expf(sc[ni][3] * 0.125f) * invl[1]) : 0.f;
            if (attn) {
                size_t arow = ((size_t)((b * H_ + h) * S_) + q0 + m0 + gid) * S_
                              + kt * 64 + cc;
                *(float2*)&attn[arow]                  = make_float2(p00, p01);
                *(float2*)&attn[arow + 8 * (size_t)S_] = make_float2(p10, p11);
            }
            int kt2 = ni >> 1, bse = (ni & 1) * 2;
            ah[kt2][bse]     = pack2h(p00, p01);
            ah[kt2][bse + 1] = pack2h(p10, p11);
        }

#pragma unroll
        for (int kt2 = 0; kt2 < 2; ++kt2)
#pragma unroll
            for (int nj = 0; nj < 8; nj += 2) {
                uint32_t b0, b1, b2, b3;
                LDSM_X4T(b0, b1, b2, b3,
                         smem_u32(&Vs_[(n0k + kt2 * 16 + (lane & 15)) * P
                                       + (nj + (lane >> 4)) * 8]));
                mma_hf(ctxc[nj],     ah[kt2], b0, b1);
                mma_hf(ctxc[nj + 1], ah[kt2], b2, b3);
            }
    }
    __syncthreads();

    // ---- pair-sum ctx across key-halves, write fp16 ----
    if (kh == 1) {
#pragma unroll
        for (int nj = 0; nj < 8; ++nj) {
            int r = m0 + gid;
            int cl = nj * 8 + 2 * tig;
            *(float2*)&sCtx[r * CTXP + cl] = make_float2(ctxc[nj][0], ctxc[nj][1]);
            *(float2*)&sCtx[(r + 8) * CTXP + cl] = make_float2(ctxc[nj][2], ctxc[nj][3]);
        }
    }
    __syncthreads();
    if (kh == 0) {
#pragma unroll
        for (int nj = 0; nj < 8; ++nj) {
            int rl = m0 + gid;
            int cl = nj * 8 + 2 * tig;
            float2 o0 = *(float2*)&sCtx[rl * CTXP + cl];
            float2 o1 = *(float2*)&sCtx[(rl + 8) * CTXP + cl];
            float v00 = ctxc[nj][0] + o0.x, v01 = ctxc[nj][1] + o0.y;
            float v10 = ctxc[nj][2] + o1.x, v11 = ctxc[nj][3] + o1.y;
            int r = q0 + rl;
            int col = h * 64 + cl;
            size_t base = ((size_t)(b * S_) + r) * D_ + col;
            *(uint32_t*)&ctxh[base]                  = pack2h(v00, v01);
            *(uint32_t*)&ctxh[base + 8 * (size_t)D_] = pack2h(v10, v11);
        }
    }
}

// ---------------------------------------------------------------------------
extern "C" void kernel_launch(void* const* d_in, const int* in_sizes, int n_in,
                              void* d_out, int out_size)
{
    const float* hs   = (const float*)d_in[0];
    const int*   mask = (const int*)  d_in[1];
    const float* Wq   = (const float*)d_in[2];
    const float* bq   = (const float*)d_in[3];
    const float* Wk   = (const float*)d_in[4];
    const float* bk   = (const float*)d_in[5];
    const float* Wv   = (const float*)d_in[6];
    const float* bv   = (const float*)d_in[7];
    const float* Wo   = (const float*)d_in[8];
    const float* bo   = (const float*)d_in[9];

    float* outp = (float*)d_out;

    half *ahp, *qfp, *kfp, *vfp, *chp, *wqp, *wkp, *wvp, *wop;
    cudaGetSymbolAddress((void**)&ahp, g_ah);
    cudaGetSymbolAddress((void**)&qfp, g_qf);
    cudaGetSymbolAddress((void**)&kfp, g_kf);
    cudaGetSymbolAddress((void**)&vfp, g_vf);
    cudaGetSymbolAddress((void**)&chp, g_ch);
    cudaGetSymbolAddress((void**)&wqp, g_wq);
    cudaGetSymbolAddress((void**)&wkp, g_wk);
    cudaGetSymbolAddress((void**)&wvp, g_wv);
    cudaGetSymbolAddress((void**)&wop, g_wo);

    float* attnp = nullptr;
    if ((long long)out_size >= OUT_ELEMS + ATTN_ELEMS)
        attnp = outp + OUT_ELEMS;

    // 1. fused casts to fp16
    {
        int n = M_ * D_ + 4 * D_ * D_;
        cast_all_kernel<<<(n + 255) / 256, 256>>>(hs, Wq, Wk, Wv, Wo,
                                                  ahp, wqp, wkp, wvp, wop);
    }

    const int gsmem = 3 * 2 * 128 * 40 * (int)sizeof(half);   // 61440
    cudaFuncSetAttribute(gemm_mma_kernel,
                         cudaFuncAttributeMaxDynamicSharedMemorySize, gsmem);

    // 2. fused Q/K/V projections (1-pass fp16)
    {
        GemmArgs3 a3;
        a3.a[0] = {ahp, wqp, bq, nullptr, qfp};
        a3.a[1] = {ahp, wkp, bk, nullptr, kfp};
        a3.a[2] = {ahp, wvp, bv, nullptr, vfp};
        dim3 gg(D_ / 128, M_ / 128, 3);
        gemm_mma_kernel<<<gg, 256, gsmem>>>(a3);
    }

    // 3. two-phase fp16 attention (phase-1 f16-acc)
    {
        dim3 ga(S_ / 64, H_, B_);
        int smA = (4608 + 3 * 2 * 4608) * (int)sizeof(half)
                  + 2048 * (int)sizeof(int) + 64 * (int)sizeof(float);  // 72960
        cudaFuncSetAttribute(attn_fp16_kernel,
                             cudaFuncAttributeMaxDynamicSharedMemorySize, smA);
        attn_fp16_kernel<<<ga, 256, smA>>>(qfp, kfp, vfp, mask, attnp, chp);
    }

    // 4. output projection (1-pass fp16)
    {
        GemmArgs3 a3;
        a3.a[0] = {chp, wop, bo, outp, nullptr};
        dim3 gg(D_ / 128, M_ / 128, 1);
        gemm_mma_kernel<<<gg, 256, gsmem>>>(a3);
    }
}

// round 17
// speedup vs baseline: 1.5662x; 1.5662x over previous
#include <cuda_runtime.h>
#include <cuda_fp16.h>
#include <cstdint>

namespace {
constexpr int B_  = 4;
constexpr int S_  = 2048;
constexpr int D_  = 1024;
constexpr int H_  = 16;
constexpr int M_  = B_ * S_;  // 8192
constexpr long long OUT_ELEMS  = (long long)M_ * D_;
constexpr long long ATTN_ELEMS = (long long)B_ * H_ * S_ * S_;
}

// ------------------------- device scratch (no allocs) -----------------------
__device__ half g_ah[M_ * D_];
__device__ half g_qf[M_ * D_], g_kf[M_ * D_], g_vf[M_ * D_];
__device__ half g_ch[M_ * D_];
__device__ half g_wq[D_ * D_], g_wk[D_ * D_], g_wv[D_ * D_], g_wo[D_ * D_];

// ----------------------------- helpers --------------------------------------
__device__ __forceinline__ uint32_t smem_u32(const void* p) {
    uint32_t a;
    asm("{ .reg .u64 t; cvta.to.shared.u64 t, %1; cvt.u32.u64 %0, t; }"
        : "=r"(a) : "l"(p));
    return a;
}

__device__ __forceinline__ void cp16(uint32_t s, const void* g) {
    asm volatile("cp.async.cg.shared.global [%0], [%1], 16;" :: "r"(s), "l"(g));
}
#define CP_COMMIT asm volatile("cp.async.commit_group;" ::: "memory")
#define CP_WAIT0  asm volatile("cp.async.wait_group 0;" ::: "memory")
#define CP_WAIT1  asm volatile("cp.async.wait_group 1;" ::: "memory")

#define LDSM_X4(r0, r1, r2, r3, addr) \
    asm volatile("ldmatrix.sync.aligned.m8n8.x4.shared.b16 {%0,%1,%2,%3}, [%4];" \
                 : "=r"(r0), "=r"(r1), "=r"(r2), "=r"(r3) : "r"(addr))

#define LDSM_X4T(r0, r1, r2, r3, addr) \
    asm volatile("ldmatrix.sync.aligned.m8n8.x4.trans.shared.b16 {%0,%1,%2,%3}, [%4];" \
                 : "=r"(r0), "=r"(r1), "=r"(r2), "=r"(r3) : "r"(addr))

__device__ __forceinline__ void mma_hf(float c[4], const uint32_t a[4],
                                       uint32_t b0, uint32_t b1) {
    asm volatile(
        "mma.sync.aligned.m16n8k16.row.col.f32.f16.f16.f32 "
        "{%0,%1,%2,%3}, {%4,%5,%6,%7}, {%8,%9}, {%0,%1,%2,%3};"
        : "+f"(c[0]), "+f"(c[1]), "+f"(c[2]), "+f"(c[3])
        : "r"(a[0]), "r"(a[1]), "r"(a[2]), "r"(a[3]), "r"(b0), "r"(b1));
}

__device__ __forceinline__ uint32_t pack2h(float x, float y) {
    __half2 t = __floats2half2_rn(x, y);
    return *reinterpret_cast<uint32_t*>(&t);
}

// ---------------------------------------------------------------------------
// Fused fp32 -> fp16 cast (vectorized: 4 floats -> 2 half2 per thread).
// Total elems = 2^23 + 4*2^20 = 12582912; /4 = 3145728 threads.
// ---------------------------------------------------------------------------
__global__ void cast_all_kernel(const float* __restrict__ hs,
                                const float* __restrict__ Wq,
                                const float* __restrict__ Wk,
                                const float* __restrict__ Wv,
                                const float* __restrict__ Wo,
                                half* __restrict__ ah,
                                half* __restrict__ wq, half* __restrict__ wk,
                                half* __restrict__ wv, half* __restrict__ wo)
{
    int q = blockIdx.x * blockDim.x + threadIdx.x;   // quad index
    constexpr int MDQ = (M_ * D_) >> 2;              // 2097152
    constexpr int DDQ = (D_ * D_) >> 2;              // 262144
    const float* src;
    half* dst;
    int off;
    if (q < MDQ) {
        src = hs; dst = ah; off = q;
    } else {
        int j = q - MDQ;
        int wsel = j / DDQ;
        off = j - wsel * DDQ;
        src = (wsel == 0) ? Wq : (wsel == 1) ? Wk : (wsel == 2) ? Wv : Wo;
        dst = (wsel == 0) ? wq : (wsel == 1) ? wk : (wsel == 2) ? wv : wo;
    }
    float4 v = *(const float4*)(src + (size_t)off * 4);
    uint32_t lo = pack2h(v.x, v.y);
    uint32_t hi = pack2h(v.z, v.w);
    *(uint2*)(dst + (size_t)off * 4) = make_uint2(lo, hi);
}

// ---------------------------------------------------------------------------
// fp16 HMMA GEMM: C = A @ W^T + bias (R13 structure; redundant bottom sync
// removed — the top sync of the next iteration orders buffer reuse).
// ---------------------------------------------------------------------------
struct GemmArgs {
    const half *Ah, *Wh;
    const float* bias;
    float* Cf;
    half* Cq;
};
struct GemmArgs3 { GemmArgs a[3]; };

__global__ void __launch_bounds__(256, 2) gemm_mma_kernel(GemmArgs3 args)
{
    constexpr int PA = 40;
    constexpr int BUFE = 128 * PA;
    constexpr int STAGE = 2 * BUFE;
    extern __shared__ __align__(16) half gsm[];

    const GemmArgs ga = args.a[blockIdx.z];

    const int tid = threadIdx.x;
    const int w = tid >> 5, lane = tid & 31, gid = lane >> 2, tig = lane & 3;
    const int bm = blockIdx.y * 128, bn = blockIdx.x * 128;
    const int m0 = (w >> 1) * 32, n0 = (w & 1) * 64;

    float c[2][8][4] = {};

    auto load_chunk = [&](int t, int buf) {
        int kc = t << 5;
        half* sA = gsm + buf * STAGE;
        half* sW = sA + BUFE;
#pragma unroll
        for (int i = 0; i < 2; ++i) {
            int idx = tid * 2 + i;
            int row = idx >> 2, q = idx & 3;
            size_t go = (size_t)row * 1024 + kc + q * 8;
            cp16(smem_u32(&sA[row * PA + q * 8]), ga.Ah + (size_t)bm * 1024 + go);
            cp16(smem_u32(&sW[row * PA + q * 8]), ga.Wh + (size_t)bn * 1024 + go);
        }
    };

    auto compute_chunk = [&](int buf) {
        const half* sA = gsm + buf * STAGE;
        const half* sW = sA + BUFE;
#pragma unroll
        for (int ks = 0; ks < 32; ks += 16) {
            uint32_t a[2][4];
#pragma unroll
            for (int mi = 0; mi < 2; ++mi) {
                int ro = (m0 + mi * 16 + (lane & 15)) * PA + ks + ((lane >> 4) << 3);
                LDSM_X4(a[mi][0], a[mi][1], a[mi][2], a[mi][3], smem_u32(&sA[ro]));
            }
#pragma unroll
            for (int p = 0; p < 4; ++p) {
                int br = n0 + p * 16 + (lane & 7) + ((lane >> 4) << 3);
                int bc = ks + (((lane >> 3) & 1) << 3);
                uint32_t b0, b1, b2, b3;
                LDSM_X4(b0, b1, b2, b3, smem_u32(&sW[br * PA + bc]));
                mma_hf(c[0][2 * p],     a[0], b0, b1);
                mma_hf(c[1][2 * p],     a[1], b0, b1);
                mma_hf(c[0][2 * p + 1], a[0], b2, b3);
                mma_hf(c[1][2 * p + 1], a[1], b2, b3);
            }
        }
    };

    load_chunk(0, 0); CP_COMMIT;
    load_chunk(1, 1); CP_COMMIT;

    for (int t = 0; t < 32; ++t) {
        if (t + 2 < 32) { CP_WAIT1; } else { CP_WAIT0; }
        __syncthreads();
        if (t + 2 < 32) { load_chunk(t + 2, (t + 2) % 3); CP_COMMIT; }
        compute_chunk(t % 3);
    }

#pragma unroll
    for (int mi = 0; mi < 2; ++mi) {
#pragma unroll
        for (int ni = 0; ni < 8; ++ni) {
            int r0 = bm + m0 + mi * 16 + gid;
            int col = bn + n0 + ni * 8 + 2 * tig;
            float bv0 = ga.bias[col], bv1 = ga.bias[col + 1];
            float o00 = c[mi][ni][0] + bv0, o01 = c[mi][ni][1] + bv1;
            float o10 = c[mi][ni][2] + bv0, o11 = c[mi][ni][3] + bv1;
            if (ga.Cf) {
                *(float2*)&ga.Cf[(size_t)r0 * 1024 + col] = make_float2(o00, o01);
                *(float2*)&ga.Cf[(size_t)(r0 + 8) * 1024 + col] = make_float2(o10, o11);
            }
            if (ga.Cq) {
                *(uint32_t*)&ga.Cq[(size_t)r0 * 1024 + col]       = pack2h(o00, o01);
                *(uint32_t*)&ga.Cq[(size_t)(r0 + 8) * 1024 + col] = pack2h(o10, o11);
            }
        }
    }
}

// ---------------------------------------------------------------------------
// Two-phase fp16 flash attention (exact R13 structure).
//   q-tile 64/CTA; 8 warps = 4 q-groups (16 rows) x 2 key-halves (32 keys).
//   3-stage K/V ring, one __syncthreads per chunk; launch_bounds(256,3).
// ---------------------------------------------------------------------------
__global__ void __launch_bounds__(256, 3) attn_fp16_kernel(
    const half* __restrict__ qf, const half* __restrict__ kf,
    const half* __restrict__ vf, const int* __restrict__ maskg,
    float* __restrict__ attn, half* __restrict__ ctxh)
{
    constexpr int P = 72;
    constexpr int KTILE = 64 * P;        // 4608 halves
    constexpr int STAGE = 2 * KTILE;     // K + V per ring stage
    constexpr int CTXP = 66;             // sCtx pitch (floats)
    extern __shared__ __align__(16) half hsm[];
    half* Qs  = hsm;                     // 64*72 = 4608 halves
    half* KV0 = hsm + 4608;              // 3 ring stages x (K,V)
    int*  sMask = (int*)(hsm + 4608 + 3 * STAGE);   // 2048 ints
    float* sL   = (float*)(sMask + 2048);           // 64 floats
    float* sCtx = (float*)KV0;           // aliases ring (post-loop)

    const int tid = threadIdx.x;
    const int w = tid >> 5, lane = tid & 31, gid = lane >> 2, tig = lane & 3;
    const int qt = blockIdx.x, h = blockIdx.y, b = blockIdx.z;
    const int q0 = qt * 64;
    const int qg = w >> 1, kh = w & 1;
    const int m0 = qg * 16;
    const int n0k = kh * 32;

    if (tid < 64) sL[tid] = 0.f;

    // ---- Q (64x64) + full mask row ----
    {
        size_t base = (size_t)(b * S_ + q0) * D_ + h * 64;
#pragma unroll
        for (int i = 0; i < 2; ++i) {
            int idx = tid * 2 + i;
            int row = idx >> 3, qq = idx & 7;
            cp16(smem_u32(&Qs[row * P + qq * 8]), qf + base + (size_t)row * D_ + qq * 8);
        }
#pragma unroll
        for (int i = 0; i < 2; ++i) {
            int j = tid * 2 + i;
            cp16(smem_u32(&sMask[j * 4]), maskg + b * S_ + j * 4);
        }
        CP_COMMIT;
    }

    auto load_k = [&](int kt, int st) {
        size_t kbase = (size_t)(b * S_ + kt * 64) * D_ + h * 64;
        half* Ks_ = KV0 + st * STAGE;
#pragma unroll
        for (int i = 0; i < 2; ++i) {
            int idx = tid * 2 + i;
            int row = idx >> 3, qq = idx & 7;
            cp16(smem_u32(&Ks_[row * P + qq * 8]), kf + kbase + (size_t)row * D_ + qq * 8);
        }
    };
    auto load_kv = [&](int kt, int st) {
        size_t kbase = (size_t)(b * S_ + kt * 64) * D_ + h * 64;
        half* Ks_ = KV0 + st * STAGE;
        half* Vs_ = Ks_ + KTILE;
#pragma unroll
        for (int i = 0; i < 2; ++i) {
            int idx = tid * 2 + i;
            int row = idx >> 3, qq = idx & 7;
            size_t go = kbase + (size_t)row * D_ + qq * 8;
            cp16(smem_u32(&Ks_[row * P + qq * 8]), kf + go);
            cp16(smem_u32(&Vs_[row * P + qq * 8]), vf + go);
        }
    };

    auto computeS = [&](const half* Ks_, float sc[4][4]) {
#pragma unroll
        for (int ks = 0; ks < 64; ks += 16) {
            uint32_t a[4];
            LDSM_X4(a[0], a[1], a[2], a[3],
                    smem_u32(&Qs[(m0 + (lane & 15)) * P + ks + ((lane >> 4) << 3)]));
#pragma unroll
            for (int p = 0; p < 2; ++p) {
                int br = n0k + p * 16 + (lane & 7) + ((lane >> 4) << 3);
                int bc = ks + (((lane >> 3) & 1) << 3);
                uint32_t b0, b1, b2, b3;
                LDSM_X4(b0, b1, b2, b3, smem_u32(&Ks_[br * P + bc]));
                mma_hf(sc[2 * p],     a, b0, b1);
                mma_hf(sc[2 * p + 1], a, b2, b3);
            }
        }
    };

    // ================= phase 1: l =================
    load_k(0, 0); CP_COMMIT;
    load_k(1, 1); CP_COMMIT;
    float lacc[2] = {};

    for (int kt = 0; kt < 32; ++kt) {
        if (kt < 31) { CP_WAIT1; } else { CP_WAIT0; }
        __syncthreads();
        if (kt + 2 < 32) { load_k(kt + 2, (kt + 2) % 3); CP_COMMIT; }

        float sc[4][4] = {};
        computeS(KV0 + (kt % 3) * STAGE, sc);

        const int* mk = sMask + kt * 64;
#pragma unroll
        for (int ni = 0; ni < 4; ++ni) {
            int cc = n0k + ni * 8 + 2 * tig;
            bool k0m = mk[cc] != 0, k1m = mk[cc + 1] != 0;
            lacc[0] += (k0m ? __expf(sc[ni][0] * 0.125f) : 0.f)
                     + (k1m ? __expf(sc[ni][1] * 0.125f) : 0.f);
            lacc[1] += (k0m ? __expf(sc[ni][2] * 0.125f) : 0.f)
                     + (k1m ? __expf(sc[ni][3] * 0.125f) : 0.f);
        }
    }

#pragma unroll
    for (int hf = 0; hf < 2; ++hf) {
        float v = lacc[hf];
        v += __shfl_xor_sync(0xffffffffu, v, 1);
        v += __shfl_xor_sync(0xffffffffu, v, 2);
        if (tig == 0) atomicAdd(&sL[m0 + gid + hf * 8], v);
    }
    __syncthreads();

    float invl[2];
#pragma unroll
    for (int hf = 0; hf < 2; ++hf) {
        float lv = sL[m0 + gid + hf * 8];
        invl[hf] = (lv > 0.f) ? (1.f / lv) : 0.f;
    }

    // ================= phase 2: attn + ctx =================
    load_kv(0, 0); CP_COMMIT;
    load_kv(1, 1); CP_COMMIT;

    float ctxc[8][4] = {};

    for (int kt = 0; kt < 32; ++kt) {
        if (kt < 31) { CP_WAIT1; } else { CP_WAIT0; }
        __syncthreads();
        if (kt + 2 < 32) { load_kv(kt + 2, (kt + 2) % 3); CP_COMMIT; }

        const half* Ks_ = KV0 + (kt % 3) * STAGE;
        const half* Vs_ = Ks_ + KTILE;

        float sc[4][4] = {};
        computeS(Ks_, sc);

        const int* mk = sMask + kt * 64;
        uint32_t ah[2][4];
#pragma unroll
        for (int ni = 0; ni < 4; ++ni) {
            int cc = n0k + ni * 8 + 2 * tig;
            bool k0m = mk[cc] != 0, k1m = mk[cc + 1] != 0;
            float p00 = k0m ? (__expf(sc[ni][0] * 0.125f) * invl[0]) : 0.f;
            float p01 = k1m ? (__expf(sc[ni][1] * 0.125f) * invl[0]) : 0.f;
            float p10 = k0m ? (__expf(sc[ni][2] * 0.125f) * invl[1]) : 0.f;
            float p11 = k1m ? (__expf(sc[ni][3] * 0.125f) * invl[1]) : 0.f;
            if (attn) {
                size_t arow = ((size_t)((b * H_ + h) * S_) + q0 + m0 + gid) * S_
                              + kt * 64 + cc;
                *(float2*)&attn[arow]                  = make_float2(p00, p01);
                *(float2*)&attn[arow + 8 * (size_t)S_] = make_float2(p10, p11);
            }
            int kt2 = ni >> 1, bse = (ni & 1) * 2;
            ah[kt2][bse]     = pack2h(p00, p01);
            ah[kt2][bse + 1] = pack2h(p10, p11);
        }

#pragma unroll
        for (int kt2 = 0; kt2 < 2; ++kt2)
#pragma unroll
            for (int nj = 0; nj < 8; nj += 2) {
                uint32_t b0, b1, b2, b3;
                LDSM_X4T(b0, b1, b2, b3,
                         smem_u32(&Vs_[(n0k + kt2 * 16 + (lane & 15)) * P
                                       + (nj + (lane >> 4)) * 8]));
                mma_hf(ctxc[nj],     ah[kt2], b0, b1);
                mma_hf(ctxc[nj + 1], ah[kt2], b2, b3);
            }
    }
    __syncthreads();

    // ---- pair-sum ctx across key-halves, write fp16 ----
    if (kh == 1) {
#pragma unroll
        for (int nj = 0; nj < 8; ++nj) {
            int r = m0 + gid;
            int cl = nj * 8 + 2 * tig;
            *(float2*)&sCtx[r * CTXP + cl] = make_float2(ctxc[nj][0], ctxc[nj][1]);
            *(float2*)&sCtx[(r + 8) * CTXP + cl] = make_float2(ctxc[nj][2], ctxc[nj][3]);
        }
    }
    __syncthreads();
    if (kh == 0) {
#pragma unroll
        for (int nj = 0; nj < 8; ++nj) {
            int rl = m0 + gid;
            int cl = nj * 8 + 2 * tig;
            float2 o0 = *(float2*)&sCtx[rl * CTXP + cl];
            float2 o1 = *(float2*)&sCtx[(rl + 8) * CTXP + cl];
            float v00 = ctxc[nj][0] + o0.x, v01 = ctxc[nj][1] + o0.y;
            float v10 = ctxc[nj][2] + o1.x, v11 = ctxc[nj][3] + o1.y;
            int r = q0 + rl;
            int col = h * 64 + cl;
            size_t base = ((size_t)(b * S_) + r) * D_ + col;
            *(uint32_t*)&ctxh[base]                  = pack2h(v00, v01);
            *(uint32_t*)&ctxh[base + 8 * (size_t)D_] = pack2h(v10, v11);
        }
    }
}

// ---------------------------------------------------------------------------
extern "C" void kernel_launch(void* const* d_in, const int* in_sizes, int n_in,
                              void* d_out, int out_size)
{
    const float* hs   = (const float*)d_in[0];
    const int*   mask = (const int*)  d_in[1];
    const float* Wq   = (const float*)d_in[2];
    const float* bq   = (const float*)d_in[3];
    const float* Wk   = (const float*)d_in[4];
    const float* bk   = (const float*)d_in[5];
    const float* Wv   = (const float*)d_in[6];
    const float* bv   = (const float*)d_in[7];
    const float* Wo   = (const float*)d_in[8];
    const float* bo   = (const float*)d_in[9];

    float* outp = (float*)d_out;

    half *ahp, *qfp, *kfp, *vfp, *chp, *wqp, *wkp, *wvp, *wop;
    cudaGetSymbolAddress((void**)&ahp, g_ah);
    cudaGetSymbolAddress((void**)&qfp, g_qf);
    cudaGetSymbolAddress((void**)&kfp, g_kf);
    cudaGetSymbolAddress((void**)&vfp, g_vf);
    cudaGetSymbolAddress((void**)&chp, g_ch);
    cudaGetSymbolAddress((void**)&wqp, g_wq);
    cudaGetSymbolAddress((void**)&wkp, g_wk);
    cudaGetSymbolAddress((void**)&wvp, g_wv);
    cudaGetSymbolAddress((void**)&wop, g_wo);

    float* attnp = nullptr;
    if ((long long)out_size >= OUT_ELEMS + ATTN_ELEMS)
        attnp = outp + OUT_ELEMS;

    // 1. fused casts to fp16 (vectorized)
    {
        int nq = (M_ * D_ + 4 * D_ * D_) / 4;
        cast_all_kernel<<<(nq + 255) / 256, 256>>>(hs, Wq, Wk, Wv, Wo,
                                                   ahp, wqp, wkp, wvp, wop);
    }

    const int gsmem = 3 * 2 * 128 * 40 * (int)sizeof(half);   // 61440
    cudaFuncSetAttribute(gemm_mma_kernel,
                         cudaFuncAttributeMaxDynamicSharedMemorySize, gsmem);

    // 2. fused Q/K/V projections (1-pass fp16)
    {
        GemmArgs3 a3;
        a3.a[0] = {ahp, wqp, bq, nullptr, qfp};
        a3.a[1] = {ahp, wkp, bk, nullptr, kfp};
        a3.a[2] = {ahp, wvp, bv, nullptr, vfp};
        dim3 gg(D_ / 128, M_ / 128, 3);
        gemm_mma_kernel<<<gg, 256, gsmem>>>(a3);
    }

    // 3. two-phase fp16 attention (R13 structure)
    {
        dim3 ga(S_ / 64, H_, B_);
        int smA = (4608 + 3 * 2 * 4608) * (int)sizeof(half)
                  + 2048 * (int)sizeof(int) + 64 * (int)sizeof(float);  // 72960
        cudaFuncSetAttribute(attn_fp16_kernel,
                             cudaFuncAttributeMaxDynamicSharedMemorySize, smA);
        attn_fp16_kernel<<<ga, 256, smA>>>(qfp, kfp, vfp, mask, attnp, chp);
    }

    // 4. output projection (1-pass fp16)
    {
        GemmArgs3 a3;
        a3.a[0] = {chp, wop, bo, outp, nullptr};
        dim3 gg(D_ / 128, M_ / 128, 1);
        gemm_mma_kernel<<<gg, 256, gsmem>>>(a3);
    }
}